// round 2
// baseline (speedup 1.0000x reference)
#include <cuda_runtime.h>
#include <math.h>

#define SZ_LOG 25
#define SZ (1u << SZ_LOG)          // 33554432
#define FD 30000000u               // FLAT_DIM
#define LOW_TILE 8192              // 2^13, low-pass tile
#define HI_C 8                     // columns per high-pass tile
#define HI_SMEM_FLOATS 33280       // 4096*8 + 64*8 padding

// Scratch (allocation-free rule: static __device__ arrays)
__device__ float g_buf0[SZ];
__device__ float g_buf1[SZ];

// ---------------------------------------------------------------------------
// Fully-unrolled in-register FWHT over 64 floats (6 butterfly stages)
// ---------------------------------------------------------------------------
__device__ __forceinline__ void fwht64(float* v) {
#pragma unroll
    for (int h = 1; h < 64; h <<= 1) {
#pragma unroll
        for (int s = 0; s < 64; s += 2 * h) {
#pragma unroll
            for (int k = 0; k < h; k++) {
                float a = v[s + k];
                float b = v[s + k + h];
                v[s + k]     = a + b;
                v[s + k + h] = a - b;
            }
        }
    }
}

// Shared-memory swizzle for the low-pass tile: XOR high bits into bank bits.
__device__ __forceinline__ int swl(int e) { return e ^ ((e >> 7) & 31); }

// ---------------------------------------------------------------------------
// Low pass: butterflies on bits 0..12 over contiguous 8192-element tiles.
// MODE 0: x = pad(theta)*B (FWHT1 front).
// MODE 1: x = src[Pi[i]]*G[i] (gather + FWHT2 front).
//   Pi/G/theta/B are single-use streams -> .cs (evict-first) so the gather
//   source (buf0, freshly written by k_high<0>) keeps L2 residency.
// ---------------------------------------------------------------------------
template <int MODE>
__global__ __launch_bounds__(128, 1) void k_low(
    const float* __restrict__ theta, const float* __restrict__ Bv,
    const float* __restrict__ src,   const int*   __restrict__ Pi,
    const float* __restrict__ G,     float*       __restrict__ dst)
{
    __shared__ float s[LOW_TILE];
    const int t = threadIdx.x;                       // 0..127
    const unsigned base = blockIdx.x * LOW_TILE;

    float v[64];
    if (MODE == 0) {
#pragma unroll
        for (int j = 0; j < 64; j++) {
            unsigned idx = base + (unsigned)j * 128u + (unsigned)t;
            float th = (idx < FD) ? __ldcs(&theta[idx]) : 0.0f;
            v[j] = th * __ldcs(&Bv[idx]);
        }
    } else {
        // Front-load all permutation indices first (max MLP), then gather.
        int pidx[64];
#pragma unroll
        for (int j = 0; j < 64; j++)
            pidx[j] = __ldcs(&Pi[base + (unsigned)j * 128u + (unsigned)t]);
#pragma unroll
        for (int j = 0; j < 64; j++) {
            unsigned idx = base + (unsigned)j * 128u + (unsigned)t;
            v[j] = __ldg(&src[pidx[j]]) * __ldcs(&G[idx]);
        }
    }

    fwht64(v);  // bits 7..12

#pragma unroll
    for (int j = 0; j < 64; j++) s[swl(j * 128 + t)] = v[j];
    __syncthreads();

    const int b6 = t >> 6;      // bit 6 owner
    const int hi = t & 63;      // bits 7..12 owner
#pragma unroll
    for (int i = 0; i < 64; i++) v[i] = s[swl(hi * 128 + b6 * 64 + i)];

    fwht64(v);  // bits 0..5

    __syncthreads();
#pragma unroll
    for (int i = 0; i < 64; i++) s[swl(hi * 128 + b6 * 64 + i)] = v[i];
    __syncthreads();

    // Final stage (bit 6) fused with coalesced store: e = i*128 + t
#pragma unroll
    for (int i = 0; i < 64; i++) {
        int e = i * 128 + t;
        float a = s[swl(e & ~64)];
        float b = s[swl(e |  64)];
        float r = (e & 64) ? (a - b) : (a + b);
        if (MODE == 1) __stcs(&dst[base + (unsigned)e], r);   // buf1: single-use stream
        else           dst[base + (unsigned)e] = r;           // buf0: keep in L2
    }
}

// ---------------------------------------------------------------------------
// High pass: butterflies on bits 13..24 (m = idx >> 13) in ONE global round
// trip. Tile = all 4096 m values x 8 consecutive low columns, 130KB smem.
// __launch_bounds__(512, 1): allow full 128 regs/thread for the v[64] pipe.
// FINAL=1: truncate to FD and apply 1/(divisor*sqrt(FD/SZ)).
// ---------------------------------------------------------------------------
__device__ __forceinline__ int sph(int m, int c) {
    return m * 8 + c + ((m >> 6) << 3);
}

template <int FINAL>
__global__ __launch_bounds__(512, 1) void k_high(
    const float* __restrict__ src, float* __restrict__ dst,
    const float* __restrict__ divisor)
{
    extern __shared__ float sh[];
    const int t = threadIdx.x;                       // 0..511
    const unsigned low_base = blockIdx.x * HI_C;

    float v[64];
    {
        const int m_hi = t >> 3, c = t & 7;
#pragma unroll
        for (int i = 0; i < 64; i++) {
            int m = m_hi * 64 + i;
            // Line is either rewritten in place (FINAL=0) or single-use
            // (FINAL=1) -> evict-first keeps L2 free for useful data.
            v[i] = __ldcs(&src[(unsigned)m * 8192u + low_base + (unsigned)c]);
        }
        fwht64(v);  // m bits 0..5  (global bits 13..18)
#pragma unroll
        for (int i = 0; i < 64; i++) sh[sph(m_hi * 64 + i, c)] = v[i];
    }
    __syncthreads();
    {
        const int m_lo = t >> 3, c = t & 7;
#pragma unroll
        for (int i = 0; i < 64; i++) v[i] = sh[sph(i * 64 + m_lo, c)];

        fwht64(v);  // m bits 6..11 (global bits 19..24)

        float scale = 1.0f;
        if (FINAL)
            scale = 1.0f / (divisor[0] * sqrtf((float)FD / (float)SZ));

#pragma unroll
        for (int i = 0; i < 64; i++) {
            int m = i * 64 + m_lo;
            unsigned idx = (unsigned)m * 8192u + low_base + (unsigned)c;
            if (FINAL) {
                if (idx < FD) __stcs(&dst[idx], v[i] * scale);
            } else {
                dst[idx] = v[i];   // buf0: gathered next -> keep in L2
            }
        }
    }
}

// ---------------------------------------------------------------------------
// kernel_launch: 4 graph-capturable launches, no allocs, no syncs.
// ---------------------------------------------------------------------------
extern "C" void kernel_launch(void* const* d_in, const int* in_sizes, int n_in,
                              void* d_out, int out_size)
{
    const float* theta   = (const float*)d_in[0];
    const float* G       = (const float*)d_in[1];
    const float* B       = (const float*)d_in[2];
    const float* divisor = (const float*)d_in[3];
    const int*   Pi      = (const int*)d_in[4];
    float*       out     = (float*)d_out;

    float *buf0, *buf1;
    cudaGetSymbolAddress((void**)&buf0, g_buf0);
    cudaGetSymbolAddress((void**)&buf1, g_buf1);

    const int smem_hi = HI_SMEM_FLOATS * (int)sizeof(float);  // 133120 B
    cudaFuncSetAttribute(k_high<0>, cudaFuncAttributeMaxDynamicSharedMemorySize, smem_hi);
    cudaFuncSetAttribute(k_high<1>, cudaFuncAttributeMaxDynamicSharedMemorySize, smem_hi);

    const int low_grid  = SZ / LOW_TILE;   // 4096
    const int high_grid = 8192 / HI_C;     // 1024

    // FWHT #1: (pad*B fused) low bits, then high bits in-place.
    k_low<0><<<low_grid, 128>>>(theta, B, nullptr, nullptr, nullptr, buf0);
    k_high<0><<<high_grid, 512, smem_hi>>>(buf0, buf0, nullptr);

    // FWHT #2: (gather via Pi, *G fused) low bits, then high bits + scale/truncate.
    k_low<1><<<low_grid, 128>>>(nullptr, nullptr, buf0, Pi, G, buf1);
    k_high<1><<<high_grid, 512, smem_hi>>>(buf1, out, divisor);
}

// round 3
// speedup vs baseline: 1.4283x; 1.4283x over previous
#include <cuda_runtime.h>
#include <cuda_fp16.h>
#include <math.h>

#define SZ_LOG 25
#define SZ (1u << SZ_LOG)          // 33554432
#define FD 30000000u               // FLAT_DIM
#define LOW_TILE 8192              // 2^13, low-pass tile
#define HI_C 8                     // columns per high-pass tile
#define HI_SMEM_FLOATS 33280       // 4096*8 + 64*8 padding

// Scratch (allocation-free rule: static __device__ arrays).
// g_buf0/g_buf1: fp32 ping-pong. g_bufh: fp16 copy of hbx for the gather
// stage — 64MB, fits L2 so the random permutation gather stays cache-resident.
__device__ float  g_buf0[SZ];
__device__ float  g_buf1[SZ];
__device__ __half g_bufh[SZ];

// ---------------------------------------------------------------------------
// Fully-unrolled in-register FWHT over 64 floats (6 butterfly stages)
// ---------------------------------------------------------------------------
__device__ __forceinline__ void fwht64(float* v) {
#pragma unroll
    for (int h = 1; h < 64; h <<= 1) {
#pragma unroll
        for (int s = 0; s < 64; s += 2 * h) {
#pragma unroll
            for (int k = 0; k < h; k++) {
                float a = v[s + k];
                float b = v[s + k + h];
                v[s + k]     = a + b;
                v[s + k + h] = a - b;
            }
        }
    }
}

// Shared-memory swizzle for the low-pass tile: XOR high bits into bank bits.
__device__ __forceinline__ int swl(int e) { return e ^ ((e >> 7) & 31); }

// ---------------------------------------------------------------------------
// Low pass: butterflies on bits 0..12 over contiguous 8192-element tiles.
// MODE 0: x = pad(theta)*B (FWHT1 front), fp32 src arrays.
// MODE 1: x = half2float(srcH[Pi[i]])*G[i] (gather + FWHT2 front).
// ---------------------------------------------------------------------------
template <int MODE>
__global__ __launch_bounds__(128) void k_low(
    const float*  __restrict__ theta, const float* __restrict__ Bv,
    const __half* __restrict__ srcH,  const int*   __restrict__ Pi,
    const float*  __restrict__ G,     float*       __restrict__ dst)
{
    __shared__ float s[LOW_TILE];
    const int t = threadIdx.x;                       // 0..127
    const unsigned base = blockIdx.x * LOW_TILE;

    float v[64];
    if (MODE == 0) {
#pragma unroll
        for (int j = 0; j < 64; j++) {
            unsigned idx = base + (unsigned)j * 128u + (unsigned)t;
            float th = (idx < FD) ? __ldcs(&theta[idx]) : 0.0f;
            v[j] = th * __ldcs(&Bv[idx]);
        }
    } else {
        // Batched index front-load (MLP) without blowing the register budget.
#pragma unroll
        for (int jb = 0; jb < 64; jb += 16) {
            int pidx[16];
#pragma unroll
            for (int k = 0; k < 16; k++)
                pidx[k] = __ldcs(&Pi[base + (unsigned)(jb + k) * 128u + (unsigned)t]);
#pragma unroll
            for (int k = 0; k < 16; k++) {
                unsigned idx = base + (unsigned)(jb + k) * 128u + (unsigned)t;
                // Random 2B gather: L2-only (L1 lines would be 98% waste).
                v[jb + k] = __half2float(__ldcg(&srcH[pidx[k]])) * __ldcs(&G[idx]);
            }
        }
    }

    fwht64(v);  // bits 7..12

#pragma unroll
    for (int j = 0; j < 64; j++) s[swl(j * 128 + t)] = v[j];
    __syncthreads();

    const int b6 = t >> 6;      // bit 6 owner
    const int hi = t & 63;      // bits 7..12 owner
#pragma unroll
    for (int i = 0; i < 64; i++) v[i] = s[swl(hi * 128 + b6 * 64 + i)];

    fwht64(v);  // bits 0..5

    __syncthreads();
#pragma unroll
    for (int i = 0; i < 64; i++) s[swl(hi * 128 + b6 * 64 + i)] = v[i];
    __syncthreads();

    // Final stage (bit 6) fused with coalesced store: e = i*128 + t
#pragma unroll
    for (int i = 0; i < 64; i++) {
        int e = i * 128 + t;
        float a = s[swl(e & ~64)];
        float b = s[swl(e |  64)];
        float r = (e & 64) ? (a - b) : (a + b);
        if (MODE == 1) __stcs(&dst[base + (unsigned)e], r);   // single-use stream
        else           dst[base + (unsigned)e] = r;
    }
}

// ---------------------------------------------------------------------------
// High pass: butterflies on bits 13..24 (m = idx >> 13) in ONE global round
// trip. Tile = all 4096 m values x 8 consecutive low columns, 130KB smem.
// MID variant writes fp16 (the array the permutation will gather from).
// FIN variant truncates to FD and applies 1/(divisor*sqrt(FD/SZ)).
// ---------------------------------------------------------------------------
__device__ __forceinline__ int sph(int m, int c) {
    return m * 8 + c + ((m >> 6) << 3);
}

__device__ __forceinline__ void k_high_core(
    const float* __restrict__ src, float* v, float* sh, int t, unsigned low_base)
{
    const int m_hi = t >> 3, c = t & 7;
#pragma unroll
    for (int i = 0; i < 64; i++) {
        int m = m_hi * 64 + i;
        v[i] = __ldcs(&src[(unsigned)m * 8192u + low_base + (unsigned)c]);
    }
    fwht64(v);  // m bits 0..5  (global bits 13..18)
#pragma unroll
    for (int i = 0; i < 64; i++) sh[sph(m_hi * 64 + i, c)] = v[i];
    __syncthreads();
    const int m_lo = t >> 3;
#pragma unroll
    for (int i = 0; i < 64; i++) v[i] = sh[sph(i * 64 + m_lo, c)];
    fwht64(v);  // m bits 6..11 (global bits 19..24)
}

__global__ __launch_bounds__(512) void k_high_mid(
    const float* __restrict__ src, __half* __restrict__ dst)
{
    extern __shared__ float sh[];
    const int t = threadIdx.x;
    const unsigned low_base = blockIdx.x * HI_C;
    float v[64];
    k_high_core(src, v, sh, t, low_base);

    const int m_lo = t >> 3, c = t & 7;
#pragma unroll
    for (int i = 0; i < 64; i++) {
        int m = i * 64 + m_lo;
        // fp16 store: keeps the gather footprint at 64MB (L2-resident).
        dst[(unsigned)m * 8192u + low_base + (unsigned)c] = __float2half_rn(v[i]);
    }
}

__global__ __launch_bounds__(512) void k_high_fin(
    const float* __restrict__ src, float* __restrict__ dst,
    const float* __restrict__ divisor)
{
    extern __shared__ float sh[];
    const int t = threadIdx.x;
    const unsigned low_base = blockIdx.x * HI_C;
    float v[64];
    k_high_core(src, v, sh, t, low_base);

    const float scale = 1.0f / (divisor[0] * sqrtf((float)FD / (float)SZ));
    const int m_lo = t >> 3, c = t & 7;
#pragma unroll
    for (int i = 0; i < 64; i++) {
        int m = i * 64 + m_lo;
        unsigned idx = (unsigned)m * 8192u + low_base + (unsigned)c;
        if (idx < FD) __stcs(&dst[idx], v[i] * scale);
    }
}

// ---------------------------------------------------------------------------
// kernel_launch: 4 graph-capturable launches, no allocs, no syncs.
// ---------------------------------------------------------------------------
extern "C" void kernel_launch(void* const* d_in, const int* in_sizes, int n_in,
                              void* d_out, int out_size)
{
    const float* theta   = (const float*)d_in[0];
    const float* G       = (const float*)d_in[1];
    const float* B       = (const float*)d_in[2];
    const float* divisor = (const float*)d_in[3];
    const int*   Pi      = (const int*)d_in[4];
    float*       out     = (float*)d_out;

    float *buf0, *buf1;  __half* bufh;
    cudaGetSymbolAddress((void**)&buf0, g_buf0);
    cudaGetSymbolAddress((void**)&buf1, g_buf1);
    cudaGetSymbolAddress((void**)&bufh, g_bufh);

    const int smem_hi = HI_SMEM_FLOATS * (int)sizeof(float);  // 133120 B
    cudaFuncSetAttribute(k_high_mid, cudaFuncAttributeMaxDynamicSharedMemorySize, smem_hi);
    cudaFuncSetAttribute(k_high_fin, cudaFuncAttributeMaxDynamicSharedMemorySize, smem_hi);

    const int low_grid  = SZ / LOW_TILE;   // 4096
    const int high_grid = 8192 / HI_C;     // 1024

    // FWHT #1: (pad*B fused) low bits -> fp32 buf0; high bits -> fp16 bufh.
    k_low<0><<<low_grid, 128>>>(theta, B, nullptr, nullptr, nullptr, buf0);
    k_high_mid<<<high_grid, 512, smem_hi>>>(buf0, bufh);

    // FWHT #2: (gather via Pi, *G fused) low bits -> buf1; high bits + scale.
    k_low<1><<<low_grid, 128>>>(nullptr, nullptr, bufh, Pi, G, buf1);
    k_high_fin<<<high_grid, 512, smem_hi>>>(buf1, out, divisor);
}

// round 5
// speedup vs baseline: 1.7435x; 1.2207x over previous
#include <cuda_runtime.h>
#include <cuda_fp16.h>
#include <math.h>

#define SZ_LOG 25
#define SZ (1u << SZ_LOG)          // 33554432
#define FD 30000000u               // FLAT_DIM
#define LOW_TILE 8192              // 2^13, low-pass tile

// fp16 range guard: FWHT2 intermediates reach std ~5e5, so pre-scale the
// second-transform data path by 2^-12 (exact in fp16) and undo at the end.
#define PRESCALE   (1.0f / 4096.0f)
#define UNPRESCALE 4096.0f

// Scratch (allocation-free rule): two fp16 ping-pong buffers, 64MB each.
__device__ __half g_h0[SZ];
__device__ __half g_h1[SZ];

// ---------------------------------------------------------------------------
// Fully-unrolled in-register FWHT over 64 floats (6 butterfly stages)
// ---------------------------------------------------------------------------
__device__ __forceinline__ void fwht64(float* v) {
#pragma unroll
    for (int h = 1; h < 64; h <<= 1) {
#pragma unroll
        for (int s = 0; s < 64; s += 2 * h) {
#pragma unroll
            for (int k = 0; k < h; k++) {
                float a = v[s + k];
                float b = v[s + k + h];
                v[s + k]     = a + b;
                v[s + k + h] = a - b;
            }
        }
    }
}

// Shared-memory swizzle for the low-pass tile: XOR high bits into bank bits.
__device__ __forceinline__ int swl(int e) { return e ^ ((e >> 7) & 31); }

// ---------------------------------------------------------------------------
// Low pass: butterflies on bits 0..12 over contiguous 8192-element tiles.
// MODE 0: x = pad(theta)*B (FWHT1 front).
// MODE 1: x = half2float(srcH[Pi[i]])*G[i]*PRESCALE (gather + FWHT2 front).
// Output fp16 (next consumer is a 6-bit streaming pass).
// ---------------------------------------------------------------------------
template <int MODE>
__global__ __launch_bounds__(128) void k_low(
    const float*  __restrict__ theta, const float* __restrict__ Bv,
    const __half* __restrict__ srcH,  const int*   __restrict__ Pi,
    const float*  __restrict__ G,     __half*      __restrict__ dst)
{
    __shared__ float s[LOW_TILE];
    const int t = threadIdx.x;                       // 0..127
    const unsigned base = blockIdx.x * LOW_TILE;

    float v[64];
    if (MODE == 0) {
#pragma unroll
        for (int j = 0; j < 64; j++) {
            unsigned idx = base + (unsigned)j * 128u + (unsigned)t;
            float th = (idx < FD) ? __ldcs(&theta[idx]) : 0.0f;
            v[j] = th * __ldcs(&Bv[idx]);
        }
    } else {
        // Batched index front-load (MLP) without blowing the register budget.
#pragma unroll
        for (int jb = 0; jb < 64; jb += 16) {
            int pidx[16];
#pragma unroll
            for (int k = 0; k < 16; k++)
                pidx[k] = __ldcs(&Pi[base + (unsigned)(jb + k) * 128u + (unsigned)t]);
#pragma unroll
            for (int k = 0; k < 16; k++) {
                unsigned idx = base + (unsigned)(jb + k) * 128u + (unsigned)t;
                // Random 2B gather over a 64MB L2-resident array: L2-only.
                v[jb + k] = __half2float(__ldcg(&srcH[pidx[k]]))
                            * (__ldcs(&G[idx]) * PRESCALE);
            }
        }
    }

    fwht64(v);  // bits 7..12

#pragma unroll
    for (int j = 0; j < 64; j++) s[swl(j * 128 + t)] = v[j];
    __syncthreads();

    const int b6 = t >> 6;      // bit 6 owner
    const int hi = t & 63;      // bits 7..12 owner
#pragma unroll
    for (int i = 0; i < 64; i++) v[i] = s[swl(hi * 128 + b6 * 64 + i)];

    fwht64(v);  // bits 0..5

    __syncthreads();
#pragma unroll
    for (int i = 0; i < 64; i++) s[swl(hi * 128 + b6 * 64 + i)] = v[i];
    __syncthreads();

    // Final stage (bit 6) fused with coalesced fp16 store: e = i*128 + t
#pragma unroll
    for (int i = 0; i < 64; i++) {
        int e = i * 128 + t;
        float a = s[swl(e & ~64)];
        float b = s[swl(e |  64)];
        float r = (e & 64) ? (a - b) : (a + b);
        __half h = __float2half_rn(r);
        if (MODE == 1) __stcs(&dst[base + (unsigned)e], h);  // protect gather-src L2
        else           dst[base + (unsigned)e] = h;
    }
}

// ---------------------------------------------------------------------------
// 6-bit streaming butterfly pass at element stride S.
// Each thread privately owns 64 elements {base + j*S}; warp loads are 64B
// contiguous runs. No shared memory, no barriers, pure MLP stream.
//   S = 8192   -> global bits 13..18
//   S = 524288 -> global bits 19..24
// FINAL=1: fp32 output truncated to FD, scaled by
//          UNPRESCALE / (divisor*sqrt(FD/SZ)).
// ---------------------------------------------------------------------------
template <unsigned S, int FINAL>
__global__ __launch_bounds__(256) void k_h6(
    __half* __restrict__ buf, float* __restrict__ out,
    const float* __restrict__ divisor)
{
    const unsigned t     = threadIdx.x;
    const unsigned cpg   = S / 256u;                 // chunks per 64*S group
    const unsigned group = blockIdx.x / cpg;
    const unsigned chunk = blockIdx.x % cpg;
    const unsigned base  = group * (S * 64u) + chunk * 256u + t;

    float v[64];
#pragma unroll
    for (int j = 0; j < 64; j++)
        v[j] = __half2float(__ldcg(&buf[base + (unsigned)j * S]));

    fwht64(v);

    if (FINAL) {
        const float scale = UNPRESCALE / (divisor[0] * sqrtf((float)FD / (float)SZ));
#pragma unroll
        for (int j = 0; j < 64; j++) {
            unsigned idx = base + (unsigned)j * S;
            if (idx < FD) __stcs(&out[idx], v[j] * scale);
        }
    } else {
#pragma unroll
        for (int j = 0; j < 64; j++)
            buf[base + (unsigned)j * S] = __float2half_rn(v[j]);
    }
}

// ---------------------------------------------------------------------------
// kernel_launch: 6 graph-capturable launches, no allocs, no syncs.
// ---------------------------------------------------------------------------
extern "C" void kernel_launch(void* const* d_in, const int* in_sizes, int n_in,
                              void* d_out, int out_size)
{
    const float* theta   = (const float*)d_in[0];
    const float* G       = (const float*)d_in[1];
    const float* B       = (const float*)d_in[2];
    const float* divisor = (const float*)d_in[3];
    const int*   Pi      = (const int*)d_in[4];
    float*       out     = (float*)d_out;

    __half *h0, *h1;
    cudaGetSymbolAddress((void**)&h0, g_h0);
    cudaGetSymbolAddress((void**)&h1, g_h1);

    const int low_grid = SZ / LOW_TILE;        // 4096
    const int h6_grid  = SZ / (64 * 256);      // 2048

    // FWHT #1: pad*B + bits 0..12 -> h0; bits 13..18; bits 19..24 (in place).
    k_low<0><<<low_grid, 128>>>(theta, B, nullptr, nullptr, nullptr, h0);
    k_h6<8192u,   0><<<h6_grid, 256>>>(h0, nullptr, nullptr);
    k_h6<524288u, 0><<<h6_grid, 256>>>(h0, nullptr, nullptr);

    // FWHT #2: gather(Pi)*G (pre-scaled) + bits 0..12 -> h1;
    //          bits 13..18; bits 19..24 + final scale.
    k_low<1><<<low_grid, 128>>>(nullptr, nullptr, h0, Pi, G, h1);
    k_h6<8192u,   0><<<h6_grid, 256>>>(h1, nullptr, nullptr);
    k_h6<524288u, 1><<<h6_grid, 256>>>(h1, out, divisor);
}

// round 6
// speedup vs baseline: 1.7822x; 1.0222x over previous
#include <cuda_runtime.h>
#include <cuda_fp16.h>
#include <math.h>

#define SZ_LOG 25
#define SZ (1u << SZ_LOG)          // 33554432
#define FD 30000000u               // FLAT_DIM
#define LOW_TILE 8192              // 2^13, low-pass tile

// fp16 range guard: FWHT2 intermediates reach std ~5e5, so pre-scale the
// second-transform data path by 2^-12 (exact in fp16) and undo at the end.
#define PRESCALE   (1.0f / 4096.0f)
#define UNPRESCALE 4096.0f

// Scratch (allocation-free rule): two fp16 ping-pong buffers, 64MB each.
__device__ __half g_h0[SZ];
__device__ __half g_h1[SZ];

// ---------------------------------------------------------------------------
// Fully-unrolled in-register FWHT over N floats
// ---------------------------------------------------------------------------
template <int N>
__device__ __forceinline__ void fwhtN(float* v) {
#pragma unroll
    for (int h = 1; h < N; h <<= 1) {
#pragma unroll
        for (int s = 0; s < N; s += 2 * h) {
#pragma unroll
            for (int k = 0; k < h; k++) {
                float a = v[s + k];
                float b = v[s + k + h];
                v[s + k]     = a + b;
                v[s + k + h] = a - b;
            }
        }
    }
}

// Shared swizzle: conflict-free for all three low-pass access patterns.
__device__ __forceinline__ int sw(int a) { return a ^ ((a >> 5) & 31); }

// ---------------------------------------------------------------------------
// Low pass: butterflies on bits 0..12 over contiguous 8192-element tiles.
// 256 threads x 32 elements/thread (occupancy-optimized: the MODE-1 gather is
// L1tex-wavefront-bound and needs many resident warps).
// Phases: fwht32 on bits 8..12 | fwht32 on bits 3..7 | fwht8 on bits 0..2.
// MODE 0: x = pad(theta)*B. MODE 1: x = srcH[Pi[i]]*G[i]*PRESCALE (gather).
// ---------------------------------------------------------------------------
template <int MODE>
__global__ __launch_bounds__(256, 3) void k_low(
    const float*  __restrict__ theta, const float* __restrict__ Bv,
    const __half* __restrict__ srcH,  const int*   __restrict__ Pi,
    const float*  __restrict__ G,     __half*      __restrict__ dst)
{
    __shared__ float s[LOW_TILE];
    const int t = threadIdx.x;                       // 0..255
    const unsigned base = blockIdx.x * LOW_TILE;

    float v[32];
    if (MODE == 0) {
#pragma unroll
        for (int j = 0; j < 32; j++) {
            unsigned idx = base + (unsigned)j * 256u + (unsigned)t;
            float th = (idx < FD) ? __ldcs(&theta[idx]) : 0.0f;
            v[j] = th * __ldcs(&Bv[idx]);
        }
    } else {
        // Batched index front-load (MLP) within the register budget.
#pragma unroll
        for (int jb = 0; jb < 32; jb += 16) {
            int pidx[16];
#pragma unroll
            for (int k = 0; k < 16; k++)
                pidx[k] = __ldcs(&Pi[base + (unsigned)(jb + k) * 256u + (unsigned)t]);
#pragma unroll
            for (int k = 0; k < 16; k++) {
                unsigned idx = base + (unsigned)(jb + k) * 256u + (unsigned)t;
                // Random 2B gather over the 64MB L2-resident array: L2-only.
                v[jb + k] = __half2float(__ldcg(&srcH[pidx[k]]))
                            * (__ldcs(&G[idx]) * PRESCALE);
            }
        }
    }

    fwhtN<32>(v);  // bits 8..12  (e = j*256 + t)

#pragma unroll
    for (int j = 0; j < 32; j++) s[sw(j * 256 + t)] = v[j];
    __syncthreads();

    // Phase B: thread owns bits 3..7; fixed bits 0..2 = t&7, bits 8..12 = t>>3.
    {
        const int m = t >> 3, r = t & 7;
#pragma unroll
        for (int k = 0; k < 32; k++) v[k] = s[sw(m * 256 + k * 8 + r)];

        fwhtN<32>(v);  // bits 3..7

#pragma unroll
        for (int k = 0; k < 32; k++) s[sw(m * 256 + k * 8 + r)] = v[k];
    }
    __syncthreads();

    // Phase C: 4 octets per thread; fwht8 on bits 0..2, 16B coalesced stores.
#pragma unroll
    for (int g = 0; g < 4; g++) {
        float w[8];
        const int ebase = g * 2048 + t * 8;
#pragma unroll
        for (int b = 0; b < 8; b++) w[b] = s[sw(ebase + b)];

        fwhtN<8>(w);   // bits 0..2

        __half h[8];
#pragma unroll
        for (int b = 0; b < 8; b++) h[b] = __float2half_rn(w[b]);

        uint4 pack = *reinterpret_cast<uint4*>(h);
        uint4* p = reinterpret_cast<uint4*>(&dst[base + (unsigned)ebase]);
        if (MODE == 1) __stcs(p, pack);   // h1 is a stream; protect gather-src L2
        else           *p = pack;         // h0 will be gathered: keep in L2
    }
}

// ---------------------------------------------------------------------------
// 6-bit streaming butterfly pass at element stride S.
// Each thread privately owns 64 elements {base + j*S}; warp loads are 64B
// contiguous runs. No shared memory, no barriers, pure MLP stream.
//   S = 8192   -> global bits 13..18
//   S = 524288 -> global bits 19..24
// FINAL=1: fp32 output truncated to FD, scaled by
//          UNPRESCALE / (divisor*sqrt(FD/SZ)).
// ---------------------------------------------------------------------------
template <unsigned S, int FINAL>
__global__ __launch_bounds__(256) void k_h6(
    __half* __restrict__ buf, float* __restrict__ out,
    const float* __restrict__ divisor)
{
    const unsigned t     = threadIdx.x;
    const unsigned cpg   = S / 256u;                 // chunks per 64*S group
    const unsigned group = blockIdx.x / cpg;
    const unsigned chunk = blockIdx.x % cpg;
    const unsigned base  = group * (S * 64u) + chunk * 256u + t;

    float v[64];
#pragma unroll
    for (int j = 0; j < 64; j++)
        v[j] = __half2float(__ldcg(&buf[base + (unsigned)j * S]));

    fwhtN<64>(v);

    if (FINAL) {
        const float scale = UNPRESCALE / (divisor[0] * sqrtf((float)FD / (float)SZ));
#pragma unroll
        for (int j = 0; j < 64; j++) {
            unsigned idx = base + (unsigned)j * S;
            if (idx < FD) __stcs(&out[idx], v[j] * scale);
        }
    } else {
#pragma unroll
        for (int j = 0; j < 64; j++)
            buf[base + (unsigned)j * S] = __float2half_rn(v[j]);
    }
}

// ---------------------------------------------------------------------------
// kernel_launch: 6 graph-capturable launches, no allocs, no syncs.
// ---------------------------------------------------------------------------
extern "C" void kernel_launch(void* const* d_in, const int* in_sizes, int n_in,
                              void* d_out, int out_size)
{
    const float* theta   = (const float*)d_in[0];
    const float* G       = (const float*)d_in[1];
    const float* B       = (const float*)d_in[2];
    const float* divisor = (const float*)d_in[3];
    const int*   Pi      = (const int*)d_in[4];
    float*       out     = (float*)d_out;

    __half *h0, *h1;
    cudaGetSymbolAddress((void**)&h0, g_h0);
    cudaGetSymbolAddress((void**)&h1, g_h1);

    const int low_grid = SZ / LOW_TILE;        // 4096
    const int h6_grid  = SZ / (64 * 256);      // 2048

    // FWHT #1: pad*B + bits 0..12 -> h0; bits 13..18; bits 19..24 (in place).
    k_low<0><<<low_grid, 256>>>(theta, B, nullptr, nullptr, nullptr, h0);
    k_h6<8192u,   0><<<h6_grid, 256>>>(h0, nullptr, nullptr);
    k_h6<524288u, 0><<<h6_grid, 256>>>(h0, nullptr, nullptr);

    // FWHT #2: gather(Pi)*G (pre-scaled) + bits 0..12 -> h1;
    //          bits 13..18; bits 19..24 + final scale.
    k_low<1><<<low_grid, 256>>>(nullptr, nullptr, h0, Pi, G, h1);
    k_h6<8192u,   0><<<h6_grid, 256>>>(h1, nullptr, nullptr);
    k_h6<524288u, 1><<<h6_grid, 256>>>(h1, out, divisor);
}